// round 13
// baseline (speedup 1.0000x reference)
#include <cuda_runtime.h>

#define NP      16384
#define NTOT    (2 * NP)
#define G       32
#define C1      (G * G * G)            // 32768 cells per cloud
#define C2      (2 * C1)               // 65536
#define GRID_LO (-4.8f)
#define H       0.3f
#define INV_H   (1.0f / 0.3f)
#define SCALE   1099511627776.0        // 2^40
#define QBLOCKS 592

typedef unsigned long long ull;

// ---------------- scratch (device globals; zero-initialized at load) -------
__device__ __align__(16) int g_counts[C2];   // invariant: zero at entry
__device__ __align__(16) int g_starts[C2 + 8];
__device__ __align__(16) int g_cursor[C2];
__device__ int    g_cells[C2];         // (chunk<<20)|cell work items
__device__ int    g_ncells;
__device__ int    g_ticket;
__device__ int    g_far[NTOT];         // queries needing brute force
__device__ int    g_nfar;
__device__ float4 g_pts[NTOT];         // cell-sorted points
__device__ ull    g_acc[2];            // fixed-point sums (B2A, A2B)

__device__ __forceinline__ int cellClamp(float v) {
    int c = (int)floorf((v - GRID_LO) * INV_H);
    return min(G - 1, max(0, c));
}

// 1) histogram; also reset per-call state
__global__ void k_count(const float* __restrict__ pred, const float* __restrict__ gt) {
    int i = blockIdx.x * blockDim.x + threadIdx.x;
    if (i == 0) { g_acc[0] = 0ull; g_acc[1] = 0ull; g_ticket = 0; g_ncells = 0; g_nfar = 0; }
    if (i >= NTOT) return;
    int cloud = i >> 14;
    int j = i & (NP - 1);
    const float* p = cloud ? gt : pred;
    float x = p[j * 3 + 0], y = p[j * 3 + 1], z = p[j * 3 + 2];
    int ci = (cellClamp(z) * G + cellClamp(y)) * G + cellClamp(x) + cloud * C1;
    atomicAdd(&g_counts[ci], 1);
}

// 2) single-block fused exclusive scan, 8 cells/thread, 8 tiles of 8192.
//    Zeroes g_counts, writes starts+cursor, builds (cell, chunk) work items.
__global__ __launch_bounds__(1024) void k_scan() {
    __shared__ int wsum[32];
    const int lane = threadIdx.x & 31, wid = threadIdx.x >> 5;
    int carry = 0;
    for (int tile = 0; tile < C2; tile += 8192) {
        const int base = tile + threadIdx.x * 8;
        int4 a = *(const int4*)&g_counts[base];
        int4 b = *(const int4*)&g_counts[base + 4];
        const int c0 = a.x, c1 = a.y, c2 = a.z, c3 = a.w;
        const int c4 = b.x, c5 = b.y, c6 = b.z, c7 = b.w;
        const int tsum = c0 + c1 + c2 + c3 + c4 + c5 + c6 + c7;
        int s = tsum;
        #pragma unroll
        for (int off = 1; off < 32; off <<= 1) {
            int n = __shfl_up_sync(0xffffffffu, s, off);
            if (lane >= off) s += n;
        }
        if (lane == 31) wsum[wid] = s;
        __syncthreads();
        if (wid == 0) {
            int ws = wsum[lane];
            #pragma unroll
            for (int off = 1; off < 32; off <<= 1) {
                int n = __shfl_up_sync(0xffffffffu, ws, off);
                if (lane >= off) ws += n;
            }
            wsum[lane] = ws;
        }
        __syncthreads();
        int o = carry + ((wid > 0) ? wsum[wid - 1] : 0) + s - tsum;
        const int o0 = o, o1 = o0 + c0, o2 = o1 + c1, o3 = o2 + c2;
        const int o4 = o3 + c3, o5 = o4 + c4, o6 = o5 + c5, o7 = o6 + c6;
        *(int4*)&g_starts[base]     = make_int4(o0, o1, o2, o3);
        *(int4*)&g_starts[base + 4] = make_int4(o4, o5, o6, o7);
        *(int4*)&g_cursor[base]     = make_int4(o0, o1, o2, o3);
        *(int4*)&g_cursor[base + 4] = make_int4(o4, o5, o6, o7);
        *(int4*)&g_counts[base]     = make_int4(0, 0, 0, 0);
        *(int4*)&g_counts[base + 4] = make_int4(0, 0, 0, 0);
        const int ch0 = (c0 + 31) >> 5, ch1 = (c1 + 31) >> 5, ch2 = (c2 + 31) >> 5,
                  ch3 = (c3 + 31) >> 5, ch4 = (c4 + 31) >> 5, ch5 = (c5 + 31) >> 5,
                  ch6 = (c6 + 31) >> 5, ch7 = (c7 + 31) >> 5;
        const int nitems = ch0 + ch1 + ch2 + ch3 + ch4 + ch5 + ch6 + ch7;
        if (nitems) {
            int pos = atomicAdd(&g_ncells, nitems);
            const int chs[8] = {ch0, ch1, ch2, ch3, ch4, ch5, ch6, ch7};
            #pragma unroll
            for (int c = 0; c < 8; c++)
                for (int k = 0; k < chs[c]; k++)
                    g_cells[pos++] = (k << 20) | (base + c);
        }
        carry += wsum[31];
        __syncthreads();
    }
    if (threadIdx.x == 0) g_starts[C2] = NTOT;
}

// 3) scatter points into cell-contiguous order
__global__ void k_scatter(const float* __restrict__ pred, const float* __restrict__ gt) {
    int i = blockIdx.x * blockDim.x + threadIdx.x;
    if (i >= NTOT) return;
    int cloud = i >> 14;
    int j = i & (NP - 1);
    const float* p = cloud ? gt : pred;
    float x = p[j * 3 + 0], y = p[j * 3 + 1], z = p[j * 3 + 2];
    int cil = (cellClamp(z) * G + cellClamp(y)) * G + cellClamp(x);
    int pos = atomicAdd(&g_cursor[cil + cloud * C1], 1);
    g_pts[pos] = make_float4(x, y, z, 0.0f);
}

// 4) dense phase: warp-per-(cell,chunk), lane-per-query, uniform broadcast
//    sweep of the 27-cell neighborhood. Queries that fail the r=1 stop bound
//    are appended to g_far (handled exactly by k_far) — NO serial ring walk.
__global__ __launch_bounds__(256) void k_query() {
    const int lane = threadIdx.x & 31;
    const int nitems = g_ncells;
    ull acc0 = 0ull, acc1 = 0ull;

    for (;;) {
        int widx = 0;
        if (lane == 0) widx = atomicAdd(&g_ticket, 1);
        widx = __shfl_sync(0xffffffffu, widx, 0);
        if (widx >= nitems) break;
        const int item = g_cells[widx];
        const int cell = item & 0xFFFFF;
        const int chunk = item >> 20;
        const int dir = (cell < C1) ? 0 : 1;     // 0: pred->gt, 1: gt->pred
        const int refbase = dir ? 0 : C1;
        const int cil = cell - (dir ? C1 : 0);
        const int cx = cil & (G - 1), cy = (cil >> 5) & (G - 1), cz = cil >> 10;

        const int qs = g_starts[cell];
        const int qe = g_starts[cell + 1];
        const int myq = qs + chunk * 32 + lane;
        const bool valid = myq < qe;

        // neighborhood row ranges: lane r<9 owns row r, broadcast on use
        const int xlo = max(cx - 1, 0), xhi = min(cx + 1, G - 1);
        int my_rs = 0, my_re = 0;
        if (lane < 9) {
            const int z = cz + lane / 3 - 1;
            const int y = cy + lane % 3 - 1;
            const bool ok = (z >= 0) & (z < G) & (y >= 0) & (y < G);
            const int rb = ok ? (refbase + (z * G + y) * G) : 0;
            my_rs = ok ? g_starts[rb + xlo] : 0;
            my_re = ok ? g_starts[rb + xhi + 1] : 0;
        }

        const float4 q = g_pts[valid ? myq : qs];
        const float qx = q.x, qy = q.y, qz = q.z;

        float best0 = 1e30f, best1 = 1e30f;
        #pragma unroll
        for (int row = 0; row < 9; row++) {
            const int s = __shfl_sync(0xffffffffu, my_rs, row);
            const int e = __shfl_sync(0xffffffffu, my_re, row);
            int j = s;
            for (; j + 1 < e; j += 2) {           // uniform broadcast loads
                const float4 p0 = g_pts[j];
                const float4 p1 = g_pts[j + 1];
                const float dx0 = qx - p0.x, dy0 = qy - p0.y, dz0 = qz - p0.z;
                const float dx1 = qx - p1.x, dy1 = qy - p1.y, dz1 = qz - p1.z;
                best0 = fminf(best0, fmaf(dx0, dx0, fmaf(dy0, dy0, dz0 * dz0)));
                best1 = fminf(best1, fmaf(dx1, dx1, fmaf(dy1, dy1, dz1 * dz1)));
            }
            if (j < e) {
                const float4 p = g_pts[j];
                const float dx = qx - p.x, dy = qy - p.y, dz = qz - p.z;
                best0 = fminf(best0, fmaf(dx, dx, fmaf(dy, dy, dz * dz)));
            }
        }
        const float best = fminf(best0, best1);

        // stop bound at r=1 (grid-clipped sides fully covered -> +inf)
        float db = 1e30f;
        if (cx - 1 > 0)     db = fminf(db, qx - (GRID_LO + (float)(cx - 1) * H));
        if (cx + 1 < G - 1) db = fminf(db, (GRID_LO + (float)(cx + 2) * H) - qx);
        if (cy - 1 > 0)     db = fminf(db, qy - (GRID_LO + (float)(cy - 1) * H));
        if (cy + 1 < G - 1) db = fminf(db, (GRID_LO + (float)(cy + 2) * H) - qy);
        if (cz - 1 > 0)     db = fminf(db, qz - (GRID_LO + (float)(cz - 1) * H));
        if (cz + 1 < G - 1) db = fminf(db, (GRID_LO + (float)(cz + 2) * H) - qz);

        if (valid) {
            if (best > db * db) {
                int pos = atomicAdd(&g_nfar, 1);   // defer to exact brute phase
                g_far[pos] = myq;
            } else {
                const ull c = (ull)((double)best * SCALE);
                if (dir == 0) acc0 += c; else acc1 += c;
            }
        }
    }

    #pragma unroll
    for (int off = 16; off > 0; off >>= 1) {
        acc0 += __shfl_xor_sync(0xffffffffu, acc0, off);
        acc1 += __shfl_xor_sync(0xffffffffu, acc1, off);
    }
    if (lane == 0) {
        if (acc0) atomicAdd(&g_acc[0], acc0);
        if (acc1) atomicAdd(&g_acc[1], acc1);
    }
}

// 5) far phase: one warp per flagged query, exact brute force over the whole
//    opposite cloud (coalesced 4-deep float4 loads, warp-reduced min).
__global__ __launch_bounds__(256) void k_far() {
    const int lane = threadIdx.x & 31;
    const int warp = (blockIdx.x * blockDim.x + threadIdx.x) >> 5;
    const int nwarps = (gridDim.x * blockDim.x) >> 5;
    const int nfar = g_nfar;
    ull acc0 = 0ull, acc1 = 0ull;

    for (int w = warp; w < nfar; w += nwarps) {
        const int qi = g_far[w];
        const int dir = (qi < NP) ? 0 : 1;
        const int rs = dir ? 0 : NP;             // opposite cloud range
        const float4 q = g_pts[qi];
        const float qx = q.x, qy = q.y, qz = q.z;
        float b0 = 1e30f, b1 = 1e30f, b2 = 1e30f, b3 = 1e30f;
        for (int j = rs + lane; j < rs + NP; j += 128) {   // 128 iters, 4-deep
            const float4 p0 = g_pts[j];
            const float4 p1 = g_pts[j + 32];
            const float4 p2 = g_pts[j + 64];
            const float4 p3 = g_pts[j + 96];
            const float dx0 = qx - p0.x, dy0 = qy - p0.y, dz0 = qz - p0.z;
            const float dx1 = qx - p1.x, dy1 = qy - p1.y, dz1 = qz - p1.z;
            const float dx2 = qx - p2.x, dy2 = qy - p2.y, dz2 = qz - p2.z;
            const float dx3 = qx - p3.x, dy3 = qy - p3.y, dz3 = qz - p3.z;
            b0 = fminf(b0, fmaf(dx0, dx0, fmaf(dy0, dy0, dz0 * dz0)));
            b1 = fminf(b1, fmaf(dx1, dx1, fmaf(dy1, dy1, dz1 * dz1)));
            b2 = fminf(b2, fmaf(dx2, dx2, fmaf(dy2, dy2, dz2 * dz2)));
            b3 = fminf(b3, fmaf(dx3, dx3, fmaf(dy3, dy3, dz3 * dz3)));
        }
        float best = fminf(fminf(b0, b1), fminf(b2, b3));
        #pragma unroll
        for (int off = 16; off > 0; off >>= 1)
            best = fminf(best, __shfl_xor_sync(0xffffffffu, best, off));
        if (lane == 0) {
            const ull c = (ull)((double)best * SCALE);
            if (dir == 0) acc0 += c; else acc1 += c;
        }
    }
    if (lane == 0) {
        if (acc0) atomicAdd(&g_acc[0], acc0);
        if (acc1) atomicAdd(&g_acc[1], acc1);
    }
}

// 6) combine
__global__ void k_final(const float* __restrict__ weight, float* __restrict__ out) {
    const double inv = 1.0 / (3.0 * (double)NP * SCALE);
    const double s0 = (double)g_acc[0] * inv;
    const double s1 = (double)g_acc[1] * inv;
    const double w = (double)weight[0];
    out[0] = (float)(w * s0 + (1.0 - w) * s1);
}

extern "C" void kernel_launch(void* const* d_in, const int* in_sizes, int n_in,
                              void* d_out, int out_size) {
    const float* pred   = (const float*)d_in[0];
    const float* gt     = (const float*)d_in[1];
    const float* weight = (const float*)d_in[2];
    float* out = (float*)d_out;
    (void)in_sizes; (void)n_in; (void)out_size;

    k_count<<<NTOT / 256, 256>>>(pred, gt);
    k_scan<<<1, 1024>>>();
    k_scatter<<<NTOT / 256, 256>>>(pred, gt);
    k_query<<<QBLOCKS, 256>>>();
    k_far<<<148, 256>>>();
    k_final<<<1, 1>>>(weight, out);
}

// round 14
// speedup vs baseline: 1.3289x; 1.3289x over previous
#include <cuda_runtime.h>

#define NP      16384
#define NTOT    (2 * NP)
#define G       32
#define C1      (G * G * G)            // 32768 cells per cloud
#define C2      (2 * C1)               // 65536
#define GRID_LO (-4.8f)
#define H       0.3f
#define INV_H   (1.0f / 0.3f)
#define SCALE   1099511627776.0        // 2^40
#define QBLOCKS 592

typedef unsigned long long ull;

// ---------------- scratch (device globals; zero-initialized at load) -------
__device__ __align__(16) int g_counts[C2];   // invariant: zero at entry
__device__ __align__(16) int g_starts[C2 + 8];
__device__ __align__(16) int g_cursor[C2];
__device__ int    g_cells[C2];         // (chunk<<20)|cell work items
__device__ int    g_ncells;
__device__ int    g_ticket;
__device__ int    g_far[NTOT];         // queries needing far search
__device__ float  g_farbest[NTOT];     // their r<=1 upper bound
__device__ int    g_nfar;
__device__ float4 g_pts[NTOT];         // cell-sorted points
__device__ ull    g_acc[2];            // fixed-point sums (B2A, A2B)

__device__ __forceinline__ int cellClamp(float v) {
    int c = (int)floorf((v - GRID_LO) * INV_H);
    return min(G - 1, max(0, c));
}

// 1) histogram; also reset per-call state
__global__ void k_count(const float* __restrict__ pred, const float* __restrict__ gt) {
    int i = blockIdx.x * blockDim.x + threadIdx.x;
    if (i == 0) { g_acc[0] = 0ull; g_acc[1] = 0ull; g_ticket = 0; g_ncells = 0; g_nfar = 0; }
    if (i >= NTOT) return;
    int cloud = i >> 14;
    int j = i & (NP - 1);
    const float* p = cloud ? gt : pred;
    float x = p[j * 3 + 0], y = p[j * 3 + 1], z = p[j * 3 + 2];
    int ci = (cellClamp(z) * G + cellClamp(y)) * G + cellClamp(x) + cloud * C1;
    atomicAdd(&g_counts[ci], 1);
}

// 2) single-block fused exclusive scan, 8 cells/thread, 8 tiles of 8192.
//    Zeroes g_counts, writes starts+cursor, builds (cell, chunk) work items.
__global__ __launch_bounds__(1024) void k_scan() {
    __shared__ int wsum[32];
    const int lane = threadIdx.x & 31, wid = threadIdx.x >> 5;
    int carry = 0;
    for (int tile = 0; tile < C2; tile += 8192) {
        const int base = tile + threadIdx.x * 8;
        int4 a = *(const int4*)&g_counts[base];
        int4 b = *(const int4*)&g_counts[base + 4];
        const int c0 = a.x, c1 = a.y, c2 = a.z, c3 = a.w;
        const int c4 = b.x, c5 = b.y, c6 = b.z, c7 = b.w;
        const int tsum = c0 + c1 + c2 + c3 + c4 + c5 + c6 + c7;
        int s = tsum;
        #pragma unroll
        for (int off = 1; off < 32; off <<= 1) {
            int n = __shfl_up_sync(0xffffffffu, s, off);
            if (lane >= off) s += n;
        }
        if (lane == 31) wsum[wid] = s;
        __syncthreads();
        if (wid == 0) {
            int ws = wsum[lane];
            #pragma unroll
            for (int off = 1; off < 32; off <<= 1) {
                int n = __shfl_up_sync(0xffffffffu, ws, off);
                if (lane >= off) ws += n;
            }
            wsum[lane] = ws;
        }
        __syncthreads();
        int o = carry + ((wid > 0) ? wsum[wid - 1] : 0) + s - tsum;
        const int o0 = o, o1 = o0 + c0, o2 = o1 + c1, o3 = o2 + c2;
        const int o4 = o3 + c3, o5 = o4 + c4, o6 = o5 + c5, o7 = o6 + c6;
        *(int4*)&g_starts[base]     = make_int4(o0, o1, o2, o3);
        *(int4*)&g_starts[base + 4] = make_int4(o4, o5, o6, o7);
        *(int4*)&g_cursor[base]     = make_int4(o0, o1, o2, o3);
        *(int4*)&g_cursor[base + 4] = make_int4(o4, o5, o6, o7);
        *(int4*)&g_counts[base]     = make_int4(0, 0, 0, 0);
        *(int4*)&g_counts[base + 4] = make_int4(0, 0, 0, 0);
        const int ch0 = (c0 + 31) >> 5, ch1 = (c1 + 31) >> 5, ch2 = (c2 + 31) >> 5,
                  ch3 = (c3 + 31) >> 5, ch4 = (c4 + 31) >> 5, ch5 = (c5 + 31) >> 5,
                  ch6 = (c6 + 31) >> 5, ch7 = (c7 + 31) >> 5;
        const int nitems = ch0 + ch1 + ch2 + ch3 + ch4 + ch5 + ch6 + ch7;
        if (nitems) {
            int pos = atomicAdd(&g_ncells, nitems);
            const int chs[8] = {ch0, ch1, ch2, ch3, ch4, ch5, ch6, ch7};
            #pragma unroll
            for (int c = 0; c < 8; c++)
                for (int k = 0; k < chs[c]; k++)
                    g_cells[pos++] = (k << 20) | (base + c);
        }
        carry += wsum[31];
        __syncthreads();
    }
    if (threadIdx.x == 0) g_starts[C2] = NTOT;
}

// 3) scatter points into cell-contiguous order
__global__ void k_scatter(const float* __restrict__ pred, const float* __restrict__ gt) {
    int i = blockIdx.x * blockDim.x + threadIdx.x;
    if (i >= NTOT) return;
    int cloud = i >> 14;
    int j = i & (NP - 1);
    const float* p = cloud ? gt : pred;
    float x = p[j * 3 + 0], y = p[j * 3 + 1], z = p[j * 3 + 2];
    int cil = (cellClamp(z) * G + cellClamp(y)) * G + cellClamp(x);
    int pos = atomicAdd(&g_cursor[cil + cloud * C1], 1);
    g_pts[pos] = make_float4(x, y, z, 0.0f);
}

// 4) dense phase: warp-per-(cell,chunk), lane-per-query, uniform broadcast
//    sweep of the 27-cell neighborhood. Queries failing the r=1 bound go to
//    g_far with their current best (exact upper bound).
__global__ __launch_bounds__(256) void k_query() {
    const int lane = threadIdx.x & 31;
    const int nitems = g_ncells;
    ull acc0 = 0ull, acc1 = 0ull;

    for (;;) {
        int widx = 0;
        if (lane == 0) widx = atomicAdd(&g_ticket, 1);
        widx = __shfl_sync(0xffffffffu, widx, 0);
        if (widx >= nitems) break;
        const int item = g_cells[widx];
        const int cell = item & 0xFFFFF;
        const int chunk = item >> 20;
        const int dir = (cell < C1) ? 0 : 1;     // 0: pred->gt, 1: gt->pred
        const int refbase = dir ? 0 : C1;
        const int cil = cell - (dir ? C1 : 0);
        const int cx = cil & (G - 1), cy = (cil >> 5) & (G - 1), cz = cil >> 10;

        const int qs = g_starts[cell];
        const int qe = g_starts[cell + 1];
        const int myq = qs + chunk * 32 + lane;
        const bool valid = myq < qe;

        const int xlo = max(cx - 1, 0), xhi = min(cx + 1, G - 1);
        int my_rs = 0, my_re = 0;
        if (lane < 9) {
            const int z = cz + lane / 3 - 1;
            const int y = cy + lane % 3 - 1;
            const bool ok = (z >= 0) & (z < G) & (y >= 0) & (y < G);
            const int rb = ok ? (refbase + (z * G + y) * G) : 0;
            my_rs = ok ? g_starts[rb + xlo] : 0;
            my_re = ok ? g_starts[rb + xhi + 1] : 0;
        }

        const float4 q = g_pts[valid ? myq : qs];
        const float qx = q.x, qy = q.y, qz = q.z;

        float best0 = 1e30f, best1 = 1e30f;
        #pragma unroll
        for (int row = 0; row < 9; row++) {
            const int s = __shfl_sync(0xffffffffu, my_rs, row);
            const int e = __shfl_sync(0xffffffffu, my_re, row);
            int j = s;
            for (; j + 1 < e; j += 2) {           // uniform broadcast loads
                const float4 p0 = g_pts[j];
                const float4 p1 = g_pts[j + 1];
                const float dx0 = qx - p0.x, dy0 = qy - p0.y, dz0 = qz - p0.z;
                const float dx1 = qx - p1.x, dy1 = qy - p1.y, dz1 = qz - p1.z;
                best0 = fminf(best0, fmaf(dx0, dx0, fmaf(dy0, dy0, dz0 * dz0)));
                best1 = fminf(best1, fmaf(dx1, dx1, fmaf(dy1, dy1, dz1 * dz1)));
            }
            if (j < e) {
                const float4 p = g_pts[j];
                const float dx = qx - p.x, dy = qy - p.y, dz = qz - p.z;
                best0 = fminf(best0, fmaf(dx, dx, fmaf(dy, dy, dz * dz)));
            }
        }
        const float best = fminf(best0, best1);

        // stop bound at r=1 (grid-clipped sides fully covered -> +inf)
        float db = 1e30f;
        if (cx - 1 > 0)     db = fminf(db, qx - (GRID_LO + (float)(cx - 1) * H));
        if (cx + 1 < G - 1) db = fminf(db, (GRID_LO + (float)(cx + 2) * H) - qx);
        if (cy - 1 > 0)     db = fminf(db, qy - (GRID_LO + (float)(cy - 1) * H));
        if (cy + 1 < G - 1) db = fminf(db, (GRID_LO + (float)(cy + 2) * H) - qy);
        if (cz - 1 > 0)     db = fminf(db, qz - (GRID_LO + (float)(cz - 1) * H));
        if (cz + 1 < G - 1) db = fminf(db, (GRID_LO + (float)(cz + 2) * H) - qz);

        if (valid) {
            if (best > db * db) {
                int pos = atomicAdd(&g_nfar, 1);   // defer to grid far phase
                g_far[pos] = myq;
                g_farbest[pos] = best;
            } else {
                const ull c = (ull)((double)best * SCALE);
                if (dir == 0) acc0 += c; else acc1 += c;
            }
        }
    }

    #pragma unroll
    for (int off = 16; off > 0; off >>= 1) {
        acc0 += __shfl_xor_sync(0xffffffffu, acc0, off);
        acc1 += __shfl_xor_sync(0xffffffffu, acc1, off);
    }
    if (lane == 0) {
        if (acc0) atomicAdd(&g_acc[0], acc0);
        if (acc1) atomicAdd(&g_acc[1], acc1);
    }
}

// 5) far phase: one warp per flagged query, warp-cooperative JUMPING-BOX
//    search. Jump straight to the box that covers the NN-sphere implied by
//    the stored upper bound; lane-per-row scan; exactness guaranteed by the
//    face-distance bound (r strictly grows; at r=G all faces clipped -> stop).
__global__ __launch_bounds__(256) void k_far() {
    const int lane = threadIdx.x & 31;
    const int warp = (blockIdx.x * blockDim.x + threadIdx.x) >> 5;
    const int nwarps = (gridDim.x * blockDim.x) >> 5;
    const int nfar = g_nfar;
    ull acc0 = 0ull, acc1 = 0ull;

    for (int w = warp; w < nfar; w += nwarps) {
        const int qi = g_far[w];
        float best = g_farbest[w];
        const int dir = (qi < NP) ? 0 : 1;
        const int refbase = dir ? 0 : C1;
        const float4 q = g_pts[qi];
        const float qx = q.x, qy = q.y, qz = q.z;
        const int cx = cellClamp(qx), cy = cellClamp(qy), cz = cellClamp(qz);

        int r = 2;
        if (best < 1e29f)
            r = max(2, (int)ceilf(sqrtf(best) * INV_H) + 1);
        if (r > G) r = G;

        for (;;) {
            const int zlo = max(cz - r, 0), zhi = min(cz + r, G - 1);
            const int ylo = max(cy - r, 0), yhi = min(cy + r, G - 1);
            const int xl  = max(cx - r, 0), xh  = min(cx + r, G - 1);
            const int ny = yhi - ylo + 1;
            const int nrows = (zhi - zlo + 1) * ny;

            float b = 1e30f;
            for (int row = lane; row < nrows; row += 32) {
                const int z = zlo + row / ny;
                const int y = ylo + row % ny;
                const int rb = refbase + (z * G + y) * G;
                const int s = g_starts[rb + xl];
                const int e = g_starts[rb + xh + 1];
                for (int j = s; j < e; j++) {
                    const float4 p = g_pts[j];
                    const float dx = qx - p.x, dy = qy - p.y, dz = qz - p.z;
                    b = fminf(b, fmaf(dx, dx, fmaf(dy, dy, dz * dz)));
                }
            }
            #pragma unroll
            for (int off = 16; off > 0; off >>= 1)
                b = fminf(b, __shfl_xor_sync(0xffffffffu, b, off));
            best = fminf(best, b);

            float db = 1e30f;   // distance to unclipped box faces
            if (cx - r > 0)     db = fminf(db, qx - (GRID_LO + (float)(cx - r) * H));
            if (cx + r < G - 1) db = fminf(db, (GRID_LO + (float)(cx + r + 1) * H) - qx);
            if (cy - r > 0)     db = fminf(db, qy - (GRID_LO + (float)(cy - r) * H));
            if (cy + r < G - 1) db = fminf(db, (GRID_LO + (float)(cy + r + 1) * H) - qy);
            if (cz - r > 0)     db = fminf(db, qz - (GRID_LO + (float)(cz - r) * H));
            if (cz + r < G - 1) db = fminf(db, (GRID_LO + (float)(cz + r + 1) * H) - qz);
            if (best <= db * db) break;

            int rneed = (best < 1e29f) ? ((int)ceilf(sqrtf(best) * INV_H) + 1) : (r + 1);
            r = max(r + 1, rneed);
            if (r > G) r = G;   // full grid; next pass db=inf -> guaranteed break
        }

        if (lane == 0) {
            const ull c = (ull)((double)fminf(best, 1e6f) * SCALE);
            if (dir == 0) acc0 += c; else acc1 += c;
        }
    }
    if (lane == 0) {
        if (acc0) atomicAdd(&g_acc[0], acc0);
        if (acc1) atomicAdd(&g_acc[1], acc1);
    }
}

// 6) combine
__global__ void k_final(const float* __restrict__ weight, float* __restrict__ out) {
    const double inv = 1.0 / (3.0 * (double)NP * SCALE);
    const double s0 = (double)g_acc[0] * inv;
    const double s1 = (double)g_acc[1] * inv;
    const double w = (double)weight[0];
    out[0] = (float)(w * s0 + (1.0 - w) * s1);
}

extern "C" void kernel_launch(void* const* d_in, const int* in_sizes, int n_in,
                              void* d_out, int out_size) {
    const float* pred   = (const float*)d_in[0];
    const float* gt     = (const float*)d_in[1];
    const float* weight = (const float*)d_in[2];
    float* out = (float*)d_out;
    (void)in_sizes; (void)n_in; (void)out_size;

    k_count<<<NTOT / 256, 256>>>(pred, gt);
    k_scan<<<1, 1024>>>();
    k_scatter<<<NTOT / 256, 256>>>(pred, gt);
    k_query<<<QBLOCKS, 256>>>();
    k_far<<<148, 256>>>();
    k_final<<<1, 1>>>(weight, out);
}